// round 1
// baseline (speedup 1.0000x reference)
#include <cuda_runtime.h>
#include <math.h>

#define DD 256      // D
#define EE 1024     // E
#define FF 1024     // F = 4*D
#define NROWS 4096  // N
#define ESPLIT 32
#define ECHUNK (EE / ESPLIT)   // 32
#define DT 16

// ---- static scratch (no allocations allowed) ----
__device__ float g_w[EE * EE];                          // 4 MB: gate logits -> softmax weights
__device__ float g_part[(size_t)ESPLIT * DD * FF];      // 32 MB: split-K partials of W_eff
__device__ float g_bpart[ESPLIT * FF];                  // 128 KB: split-K partials of b_eff
__device__ float g_Weff[DD * FF];                       // 1 MB
__device__ float g_beff[FF];                            // 4 KB

// ============================================================
// Kernel 1: gate GEMM  L[i,j] = x[i,:] @ gate_W[:,j] + gate_b[j]
// for i in [0,1024). 64x64 tile, 256 threads, 4x4 per thread.
// ============================================================
__global__ void gate_gemm(const float* __restrict__ x,
                          const float* __restrict__ gW,
                          const float* __restrict__ gb) {
    __shared__ float As[16][68];   // [k][i], padded
    __shared__ float Bs[16][64];   // [k][j]
    const int tid = threadIdx.x;
    const int i0 = blockIdx.y * 64;
    const int j0 = blockIdx.x * 64;
    const int tx = tid & 15;
    const int ty = tid >> 4;

    float acc[4][4];
#pragma unroll
    for (int r = 0; r < 4; r++)
#pragma unroll
        for (int c = 0; c < 4; c++) acc[r][c] = 0.f;

    for (int k0 = 0; k0 < DD; k0 += 16) {
#pragma unroll
        for (int t = 0; t < 4; t++) {
            int m = tid + t * 256;
            int r = m >> 4, c = m & 15;
            As[c][r] = x[(size_t)(i0 + r) * DD + k0 + c];
        }
#pragma unroll
        for (int t = 0; t < 4; t++) {
            int m = tid + t * 256;
            int r = m >> 6, c = m & 63;
            Bs[r][c] = gW[(size_t)(k0 + r) * EE + j0 + c];
        }
        __syncthreads();
#pragma unroll
        for (int k = 0; k < 16; k++) {
            float a[4], b[4];
#pragma unroll
            for (int r = 0; r < 4; r++) a[r] = As[k][ty * 4 + r];
#pragma unroll
            for (int c = 0; c < 4; c++) b[c] = Bs[k][tx * 4 + c];
#pragma unroll
            for (int r = 0; r < 4; r++)
#pragma unroll
                for (int c = 0; c < 4; c++) acc[r][c] += a[r] * b[c];
        }
        __syncthreads();
    }

#pragma unroll
    for (int r = 0; r < 4; r++) {
        int gi = i0 + ty * 4 + r;
        int gj = j0 + tx * 4;
        float4 v;
        v.x = acc[r][0] + gb[gj + 0];
        v.y = acc[r][1] + gb[gj + 1];
        v.z = acc[r][2] + gb[gj + 2];
        v.w = acc[r][3] + gb[gj + 3];
        *(float4*)&g_w[(size_t)gi * EE + gj] = v;
    }
}

// ============================================================
// Kernel 2: row softmax in-place on g_w (1024 rows x 1024)
// one CTA (256 threads) per row, each thread owns a float4.
// ============================================================
__global__ void softmax_rows() {
    const int row = blockIdx.x;
    const int tid = threadIdx.x;
    const int lane = tid & 31;
    const int wid = tid >> 5;
    float4* p = ((float4*)g_w) + (size_t)row * (EE / 4);
    float4 v = p[tid];

    __shared__ float red[8];
    __shared__ float bc;

    // max
    float m = fmaxf(fmaxf(v.x, v.y), fmaxf(v.z, v.w));
#pragma unroll
    for (int o = 16; o > 0; o >>= 1) m = fmaxf(m, __shfl_xor_sync(0xffffffffu, m, o));
    if (lane == 0) red[wid] = m;
    __syncthreads();
    if (tid == 0) {
        float t = red[0];
#pragma unroll
        for (int i = 1; i < 8; i++) t = fmaxf(t, red[i]);
        bc = t;
    }
    __syncthreads();
    m = bc;
    __syncthreads();

    // exp + sum
    v.x = expf(v.x - m); v.y = expf(v.y - m);
    v.z = expf(v.z - m); v.w = expf(v.w - m);
    float s = v.x + v.y + v.z + v.w;
#pragma unroll
    for (int o = 16; o > 0; o >>= 1) s += __shfl_xor_sync(0xffffffffu, s, o);
    if (lane == 0) red[wid] = s;
    __syncthreads();
    if (tid == 0) {
        float t = 0.f;
#pragma unroll
        for (int i = 0; i < 8; i++) t += red[i];
        bc = t;
    }
    __syncthreads();
    float inv = 1.f / bc;
    v.x *= inv; v.y *= inv; v.z *= inv; v.w *= inv;
    p[tid] = v;
}

// ============================================================
// Kernel 3: split-K W_eff partials (the HBM-bound stream).
// grid (D/DT, ESPLIT), 256 threads; thread owns f4 = tid (float4 of f).
// part[es][d][f] = sum_{e in chunk} w[e,f] * expert_W[e,d,f]
// ============================================================
__global__ void weff_partial(const float* __restrict__ eW) {
    const int tid = threadIdx.x;                  // 0..255 -> f4
    const int d0 = blockIdx.x * DT;
    const int es = blockIdx.y;
    const int e0 = es * ECHUNK;

    float4 acc[DT];
#pragma unroll
    for (int i = 0; i < DT; i++) acc[i] = make_float4(0.f, 0.f, 0.f, 0.f);

    const float4* wbase = ((const float4*)g_w) + (size_t)e0 * (FF / 4) + tid;
    const float4* ebase = ((const float4*)eW) + ((size_t)e0 * DD + d0) * (FF / 4) + tid;

    for (int e = 0; e < ECHUNK; e++) {
        float4 wv = wbase[(size_t)e * (FF / 4)];
        const float4* ep = ebase + (size_t)e * DD * (FF / 4);
#pragma unroll
        for (int dd = 0; dd < DT; dd++) {
            float4 ev = ep[(size_t)dd * (FF / 4)];
            acc[dd].x += wv.x * ev.x;
            acc[dd].y += wv.y * ev.y;
            acc[dd].z += wv.z * ev.z;
            acc[dd].w += wv.w * ev.w;
        }
    }

    float4* outp = ((float4*)g_part) + ((size_t)es * DD + d0) * (FF / 4) + tid;
#pragma unroll
    for (int dd = 0; dd < DT; dd++) outp[(size_t)dd * (FF / 4)] = acc[dd];
}

// ============================================================
// Kernel 4: split-K b_eff partials. grid ESPLIT, 256 threads.
// ============================================================
__global__ void beff_partial(const float* __restrict__ eb) {
    const int tid = threadIdx.x;
    const int es = blockIdx.x;
    const int e0 = es * ECHUNK;
    float4 acc = make_float4(0.f, 0.f, 0.f, 0.f);
    const float4* wbase = ((const float4*)g_w) + (size_t)e0 * (FF / 4) + tid;
    const float4* bbase = ((const float4*)eb) + (size_t)e0 * (FF / 4) + tid;
    for (int e = 0; e < ECHUNK; e++) {
        float4 wv = wbase[(size_t)e * (FF / 4)];
        float4 bv = bbase[(size_t)e * (FF / 4)];
        acc.x += wv.x * bv.x;
        acc.y += wv.y * bv.y;
        acc.z += wv.z * bv.z;
        acc.w += wv.w * bv.w;
    }
    ((float4*)g_bpart)[(size_t)es * (FF / 4) + tid] = acc;
}

// ============================================================
// Kernel 5: deterministic fixed-order reduction of partials.
// ============================================================
__global__ void reduce_parts() {
    const int idx = blockIdx.x * blockDim.x + threadIdx.x;  // over D*F/4
    if (idx < DD * FF / 4) {
        float4 s = make_float4(0.f, 0.f, 0.f, 0.f);
#pragma unroll 4
        for (int p = 0; p < ESPLIT; p++) {
            float4 v = ((const float4*)g_part)[(size_t)p * (DD * FF / 4) + idx];
            s.x += v.x; s.y += v.y; s.z += v.z; s.w += v.w;
        }
        ((float4*)g_Weff)[idx] = s;
    }
    if (idx < FF / 4) {
        float4 s = make_float4(0.f, 0.f, 0.f, 0.f);
#pragma unroll 4
        for (int p = 0; p < ESPLIT; p++) {
            float4 v = ((const float4*)g_bpart)[(size_t)p * (FF / 4) + idx];
            s.x += v.x; s.y += v.y; s.z += v.z; s.w += v.w;
        }
        ((float4*)g_beff)[idx] = s;
    }
}

// ============================================================
// Kernel 6: final GEMM  out = x @ W_eff + b_eff
// M=4096, N=1024, K=256. 128x128 tile, BK=8, 256 threads, 8x8/thread.
// ============================================================
__global__ void final_gemm(const float* __restrict__ x, float* __restrict__ out) {
    __shared__ float As[8][132];   // [k][i], padded
    __shared__ float Bs[8][128];   // [k][j]
    const int tid = threadIdx.x;
    const int i0 = blockIdx.y * 128;
    const int j0 = blockIdx.x * 128;
    const int tx = tid & 15;    // j: 16 * 8 = 128
    const int ty = tid >> 4;    // i: 16 * 8 = 128

    float acc[8][8];
#pragma unroll
    for (int r = 0; r < 8; r++)
#pragma unroll
        for (int c = 0; c < 8; c++) acc[r][c] = 0.f;

    for (int k0 = 0; k0 < DD; k0 += 8) {
        {   // A tile: 128 rows x 8 k
            int r = tid >> 1;
            int c = (tid & 1) * 4;
            float4 v = *(const float4*)&x[(size_t)(i0 + r) * DD + k0 + c];
            As[c + 0][r] = v.x;
            As[c + 1][r] = v.y;
            As[c + 2][r] = v.z;
            As[c + 3][r] = v.w;
        }
        {   // B tile: 8 k x 128 j
            int r = tid >> 5;
            int c = (tid & 31) * 4;
            *(float4*)&Bs[r][c] = *(const float4*)&g_Weff[(size_t)(k0 + r) * FF + j0 + c];
        }
        __syncthreads();
#pragma unroll
        for (int k = 0; k < 8; k++) {
            float a[8], b[8];
            *(float4*)&a[0] = *(const float4*)&As[k][ty * 8];
            *(float4*)&a[4] = *(const float4*)&As[k][ty * 8 + 4];
            *(float4*)&b[0] = *(const float4*)&Bs[k][tx * 8];
            *(float4*)&b[4] = *(const float4*)&Bs[k][tx * 8 + 4];
#pragma unroll
            for (int r = 0; r < 8; r++)
#pragma unroll
                for (int c = 0; c < 8; c++) acc[r][c] += a[r] * b[c];
        }
        __syncthreads();
    }

    // epilogue: bias + store
    float bias[8];
#pragma unroll
    for (int c = 0; c < 8; c++) bias[c] = g_beff[j0 + tx * 8 + c];
#pragma unroll
    for (int r = 0; r < 8; r++) {
        int gi = i0 + ty * 8 + r;
        float4 v0, v1;
        v0.x = acc[r][0] + bias[0];
        v0.y = acc[r][1] + bias[1];
        v0.z = acc[r][2] + bias[2];
        v0.w = acc[r][3] + bias[3];
        v1.x = acc[r][4] + bias[4];
        v1.y = acc[r][5] + bias[5];
        v1.z = acc[r][6] + bias[6];
        v1.w = acc[r][7] + bias[7];
        *(float4*)&out[(size_t)gi * FF + j0 + tx * 8] = v0;
        *(float4*)&out[(size_t)gi * FF + j0 + tx * 8 + 4] = v1;
    }
}

// ============================================================
extern "C" void kernel_launch(void* const* d_in, const int* in_sizes, int n_in,
                              void* d_out, int out_size) {
    const float* x  = (const float*)d_in[0];   // (4096, 256)
    const float* gW = (const float*)d_in[1];   // (256, 1024)
    const float* gb = (const float*)d_in[2];   // (1024,)
    const float* eW = (const float*)d_in[3];   // (1024, 256, 1024)
    const float* eb = (const float*)d_in[4];   // (1024, 1024)
    float* out = (float*)d_out;                // (4096, 1024)

    gate_gemm<<<dim3(EE / 64, EE / 64), 256>>>(x, gW, gb);
    softmax_rows<<<EE, 256>>>();
    weff_partial<<<dim3(DD / DT, ESPLIT), 256>>>(eW);
    beff_partial<<<ESPLIT, 256>>>(eb);
    reduce_parts<<<(DD * FF / 4) / 256, 256>>>();
    final_gemm<<<dim3(FF / 128, NROWS / 128), 256>>>(x, out);
}